// round 1
// baseline (speedup 1.0000x reference)
#include <cuda_runtime.h>
#include <math.h>

#define S_LEN 2048
#define DMODEL 1024
#define NHEADS 16
#define HDIM 64
#define RADIUS 256
#define NGLOB 4

// scratch: 5 projection outputs (Q,K,V,KG,VG) + attention output O
__device__ float g_P[(size_t)5 * S_LEN * DMODEL];
__device__ float g_O[(size_t)S_LEN * DMODEL];

struct W5 { const float* w[5]; };

// ---------------------------------------------------------------------------
// SGEMM: C[2048,1024] = A[2048,1024] @ B[1024,1024], fp32, 128x128x8 tiles
// ---------------------------------------------------------------------------
#define BM 128
#define BN 128
#define BK 8

__device__ __forceinline__ void sgemm_tile(const float* __restrict__ A,
                                           const float* __restrict__ B,
                                           float* __restrict__ C)
{
    const int N = DMODEL, K = DMODEL;
    __shared__ float As[BK][BM + 4];
    __shared__ float Bs[BK][BN + 4];

    int tid = threadIdx.x;
    int bx = blockIdx.x, by = blockIdx.y;

    int arow = tid >> 1;            // 0..127
    int acol = (tid & 1) << 2;      // 0 or 4
    int brow = tid >> 5;            // 0..7
    int bcol = (tid & 31) << 2;     // 0..124

    const float* Ap = A + (size_t)(by * BM + arow) * K + acol;
    const float* Bp = B + (size_t)brow * N + bx * BN + bcol;

    int ty = (tid >> 4) << 3;       // 0..120
    int tx = (tid & 15) << 3;       // 0..120

    float acc[8][8];
#pragma unroll
    for (int i = 0; i < 8; i++)
#pragma unroll
        for (int j = 0; j < 8; j++) acc[i][j] = 0.f;

    for (int k0 = 0; k0 < K; k0 += BK) {
        float4 av = *(const float4*)(Ap + k0);
        As[acol + 0][arow] = av.x;
        As[acol + 1][arow] = av.y;
        As[acol + 2][arow] = av.z;
        As[acol + 3][arow] = av.w;
        *(float4*)&Bs[brow][bcol] = *(const float4*)(Bp + (size_t)k0 * N);
        __syncthreads();
#pragma unroll
        for (int kk = 0; kk < BK; kk++) {
            float4 a0 = *(const float4*)&As[kk][ty];
            float4 a1 = *(const float4*)&As[kk][ty + 4];
            float4 b0 = *(const float4*)&Bs[kk][tx];
            float4 b1 = *(const float4*)&Bs[kk][tx + 4];
            float ar[8] = {a0.x, a0.y, a0.z, a0.w, a1.x, a1.y, a1.z, a1.w};
            float br[8] = {b0.x, b0.y, b0.z, b0.w, b1.x, b1.y, b1.z, b1.w};
#pragma unroll
            for (int i = 0; i < 8; i++)
#pragma unroll
                for (int j = 0; j < 8; j++)
                    acc[i][j] = fmaf(ar[i], br[j], acc[i][j]);
        }
        __syncthreads();
    }

#pragma unroll
    for (int i = 0; i < 8; i++) {
        float* Cp = C + (size_t)(by * BM + ty + i) * N + bx * BN + tx;
        *(float4*)Cp       = make_float4(acc[i][0], acc[i][1], acc[i][2], acc[i][3]);
        *(float4*)(Cp + 4) = make_float4(acc[i][4], acc[i][5], acc[i][6], acc[i][7]);
    }
}

__global__ __launch_bounds__(256) void proj_kernel(const float* __restrict__ x, W5 ws)
{
    const float* B = ws.w[blockIdx.z];
    float* C = g_P + (size_t)blockIdx.z * S_LEN * DMODEL;
    sgemm_tile(x, B, C);
}

__global__ __launch_bounds__(256) void out_gemm_kernel(const float* __restrict__ Wo,
                                                       float* __restrict__ out)
{
    sgemm_tile(g_O, Wo, out);
}

// ---------------------------------------------------------------------------
// RoPE on Q (slot 0) and K (slot 1), in place.
// thread handles pair (d, d+32) of one (s, h).
// ---------------------------------------------------------------------------
__global__ __launch_bounds__(256) void rope_kernel(const float* __restrict__ cos_t,
                                                   const float* __restrict__ sin_t,
                                                   const int* __restrict__ pos)
{
    int idx = blockIdx.x * blockDim.x + threadIdx.x;  // S*H*32 threads
    int d = idx & 31;
    int h = (idx >> 5) & (NHEADS - 1);
    int s = idx >> 9;
    if (s >= S_LEN) return;
    int p = pos[s];

    float c0 = cos_t[p * HDIM + d];
    float c1 = cos_t[p * HDIM + d + 32];
    float s0 = sin_t[p * HDIM + d];
    float s1 = sin_t[p * HDIM + d + 32];

    float* base = g_P + (size_t)blockIdx.y * S_LEN * DMODEL + (size_t)s * DMODEL + h * HDIM;
    float x0 = base[d];
    float x1 = base[d + 32];
    base[d]      = x0 * c0 - x1 * s0;
    base[d + 32] = x1 * c1 + x0 * s1;
}

// ---------------------------------------------------------------------------
// Fused local (sliding-window + global-column boost) + global attention.
// One warp per (query i, head h). Online softmax over the window, exactly
// mirroring reference fp32 semantics (+1e9 on cols 0..3 in-window; score 0
// for cols 0..3 out-of-window).
// ---------------------------------------------------------------------------
__global__ __launch_bounds__(128) void attn_kernel()
{
    int warp = (blockIdx.x * blockDim.x + threadIdx.x) >> 5;
    int lane = threadIdx.x & 31;
    int h = warp & (NHEADS - 1);
    int i = warp >> 4;
    if (i >= S_LEN) return;

    const float scale = 0.125f;  // 1/sqrt(64)
    const float* Q  = g_P;
    const float* K  = g_P + (size_t)1 * S_LEN * DMODEL;
    const float* V  = g_P + (size_t)2 * S_LEN * DMODEL;
    const float* KG = g_P + (size_t)3 * S_LEN * DMODEL;
    const float* VG = g_P + (size_t)4 * S_LEN * DMODEL;

    const float* qp = Q + (size_t)i * DMODEL + h * HDIM;
    float q0 = qp[lane], q1 = qp[lane + 32];

    int jlo = i - RADIUS; if (jlo < 0) jlo = 0;

    float m = -3.4e38f, sum = 0.f, a0 = 0.f, a1 = 0.f;

    for (int j = jlo; j <= i; j++) {
        const float* kp = K + (size_t)j * DMODEL + h * HDIM;
        float p = q0 * kp[lane] + q1 * kp[lane + 32];
#pragma unroll
        for (int o = 16; o > 0; o >>= 1) p += __shfl_xor_sync(0xffffffff, p, o);
        float s = p * scale;
        if (j < NGLOB) s += 1e9f;

        float mn = fmaxf(m, s);
        float esc = __expf(m - mn);
        float e = __expf(s - mn);
        const float* vp = V + (size_t)j * DMODEL + h * HDIM;
        sum = sum * esc + e;
        a0  = a0 * esc + e * vp[lane];
        a1  = a1 * esc + e * vp[lane + 32];
        m = mn;
    }
    // global columns outside the window contribute score exactly 0
#pragma unroll
    for (int j = 0; j < NGLOB; j++) {
        if (j >= jlo && j <= i) continue;
        float s = 0.f;
        float mn = fmaxf(m, s);
        float esc = __expf(m - mn);
        float e = __expf(s - mn);
        const float* vp = V + (size_t)j * DMODEL + h * HDIM;
        sum = sum * esc + e;
        a0  = a0 * esc + e * vp[lane];
        a1  = a1 * esc + e * vp[lane + 32];
        m = mn;
    }
    float inv = 1.f / sum;
    float o0 = a0 * inv;
    float o1 = a1 * inv;

    // global attention: softmax over the 4 global columns of KG/VG
    float sg[NGLOB];
    float mg = -3.4e38f;
#pragma unroll
    for (int t = 0; t < NGLOB; t++) {
        const float* kp = KG + (size_t)t * DMODEL + h * HDIM;
        float p = q0 * kp[lane] + q1 * kp[lane + 32];
#pragma unroll
        for (int o = 16; o > 0; o >>= 1) p += __shfl_xor_sync(0xffffffff, p, o);
        sg[t] = p * scale;
        mg = fmaxf(mg, sg[t]);
    }
    float den = 0.f, gsum0 = 0.f, gsum1 = 0.f;
#pragma unroll
    for (int t = 0; t < NGLOB; t++) {
        float e = __expf(sg[t] - mg);
        const float* vp = VG + (size_t)t * DMODEL + h * HDIM;
        den += e;
        gsum0 += e * vp[lane];
        gsum1 += e * vp[lane + 32];
    }
    float ginv = 1.f / den;
    o0 += gsum0 * ginv;
    o1 += gsum1 * ginv;

    float* op = g_O + (size_t)i * DMODEL + h * HDIM;
    op[lane]      = o0;
    op[lane + 32] = o1;
}

// ---------------------------------------------------------------------------
// launch
// ---------------------------------------------------------------------------
extern "C" void kernel_launch(void* const* d_in, const int* in_sizes, int n_in,
                              void* d_out, int out_size)
{
    const float* x     = (const float*)d_in[0];
    const float* cos_t = (const float*)d_in[1];
    const float* sin_t = (const float*)d_in[2];
    const int*   pos   = (const int*)d_in[3];
    W5 ws;
    ws.w[0] = (const float*)d_in[4];   // Wqs -> Q
    ws.w[1] = (const float*)d_in[5];   // Wks -> K
    ws.w[2] = (const float*)d_in[6];   // Wvs -> V
    ws.w[3] = (const float*)d_in[8];   // Wkg -> KG   (d_in[7] = Wqg, unused)
    ws.w[4] = (const float*)d_in[9];   // Wvg -> VG
    const float* Wo = (const float*)d_in[10];
    float* out = (float*)d_out;

    dim3 gp(DMODEL / BN, S_LEN / BM, 5);
    proj_kernel<<<gp, 256>>>(x, ws);

    dim3 gr((S_LEN * NHEADS * 32) / 256, 2);
    rope_kernel<<<gr, 256>>>(cos_t, sin_t, pos);

    attn_kernel<<<(S_LEN * NHEADS) / 4, 128>>>();

    dim3 go(DMODEL / BN, S_LEN / BM);
    out_gemm_kernel<<<go, 256>>>(Wo, out);
}

// round 2
// speedup vs baseline: 1.0053x; 1.0053x over previous
#include <cuda_runtime.h>
#include <math.h>

#define S_LEN 2048
#define DMODEL 1024
#define NHEADS 16
#define HDIM 64
#define RADIUS 256
#define NGLOB 4

// scratch: 5 projection outputs (Q,K,V,KG,VG) + attention output O
__device__ float g_P[(size_t)5 * S_LEN * DMODEL];
__device__ float g_O[(size_t)S_LEN * DMODEL];

struct W5 { const float* w[5]; };

// ---------------------------------------------------------------------------
// 3xTF32 GEMM: C[2048,1024] = A[2048,1024] @ B[1024,1024]
// block 128x128x16, 8 warps (4M x 2N), warp tile 32x64, mma.m16n8k8.tf32
// ---------------------------------------------------------------------------
#define GBM 128
#define GBN 128
#define GBK 16
#define ASTRIDE (GBK + 4)    // 20 -> conflict-free A-fragment reads
#define BSTRIDE (GBN + 8)    // 136 -> conflict-free B-fragment reads

__device__ __forceinline__ unsigned f2tf32(float x) {
    unsigned r;
    asm("cvt.rna.tf32.f32 %0, %1;" : "=r"(r) : "f"(x));
    return r;
}

__device__ __forceinline__ void mma_tf32(float* c, const unsigned* a, const unsigned* b) {
    asm volatile(
        "mma.sync.aligned.m16n8k8.row.col.f32.tf32.tf32.f32 "
        "{%0,%1,%2,%3}, {%4,%5,%6,%7}, {%8,%9}, {%0,%1,%2,%3};"
        : "+f"(c[0]), "+f"(c[1]), "+f"(c[2]), "+f"(c[3])
        : "r"(a[0]), "r"(a[1]), "r"(a[2]), "r"(a[3]), "r"(b[0]), "r"(b[1]));
}

__device__ __forceinline__ void tf32_gemm_tile(const float* __restrict__ A,
                                               const float* __restrict__ B,
                                               float* __restrict__ C)
{
    const int K = DMODEL, N = DMODEL;
    __shared__ unsigned Ah[GBM * ASTRIDE];
    __shared__ unsigned Al[GBM * ASTRIDE];
    __shared__ unsigned Bh[GBK * BSTRIDE];
    __shared__ unsigned Bl[GBK * BSTRIDE];

    int tid = threadIdx.x;
    int lane = tid & 31;
    int warp = tid >> 5;
    int wm = warp >> 1;      // 0..3
    int wn = warp & 1;       // 0..1
    int bx = blockIdx.x, by = blockIdx.y;

    float acc[2][8][4];
#pragma unroll
    for (int mt = 0; mt < 2; mt++)
#pragma unroll
        for (int nt = 0; nt < 8; nt++)
#pragma unroll
            for (int e = 0; e < 4; e++) acc[mt][nt][e] = 0.f;

    for (int k0 = 0; k0 < K; k0 += GBK) {
        // ---- load A tile [128 x 16], split hi/lo ----
#pragma unroll
        for (int it = 0; it < 2; it++) {
            int l = tid + it * 256;           // float4 index, 512 total
            int m = l >> 2;
            int kq = (l & 3) << 2;
            float4 v = *(const float4*)(A + (size_t)(by * GBM + m) * K + k0 + kq);
            float f[4] = {v.x, v.y, v.z, v.w};
#pragma unroll
            for (int e = 0; e < 4; e++) {
                unsigned h = f2tf32(f[e]);
                float lo = f[e] - __uint_as_float(h);
                Ah[m * ASTRIDE + kq + e] = h;
                Al[m * ASTRIDE + kq + e] = f2tf32(lo);
            }
        }
        // ---- load B tile [16 x 128], split hi/lo ----
#pragma unroll
        for (int it = 0; it < 2; it++) {
            int l = tid + it * 256;
            int k = l >> 5;
            int nq = (l & 31) << 2;
            float4 v = *(const float4*)(B + (size_t)(k0 + k) * N + bx * GBN + nq);
            float f[4] = {v.x, v.y, v.z, v.w};
#pragma unroll
            for (int e = 0; e < 4; e++) {
                unsigned h = f2tf32(f[e]);
                float lo = f[e] - __uint_as_float(h);
                Bh[k * BSTRIDE + nq + e] = h;
                Bl[k * BSTRIDE + nq + e] = f2tf32(lo);
            }
        }
        __syncthreads();

#pragma unroll
        for (int ks = 0; ks < GBK; ks += 8) {
            unsigned ah[2][4], al[2][4], bh[8][2], bl[8][2];
#pragma unroll
            for (int mt = 0; mt < 2; mt++) {
                int r = wm * 32 + mt * 16 + (lane >> 2);
                int c = ks + (lane & 3);
                ah[mt][0] = Ah[r * ASTRIDE + c];
                ah[mt][1] = Ah[(r + 8) * ASTRIDE + c];
                ah[mt][2] = Ah[r * ASTRIDE + c + 4];
                ah[mt][3] = Ah[(r + 8) * ASTRIDE + c + 4];
                al[mt][0] = Al[r * ASTRIDE + c];
                al[mt][1] = Al[(r + 8) * ASTRIDE + c];
                al[mt][2] = Al[r * ASTRIDE + c + 4];
                al[mt][3] = Al[(r + 8) * ASTRIDE + c + 4];
            }
#pragma unroll
            for (int nt = 0; nt < 8; nt++) {
                int n = wn * 64 + nt * 8 + (lane >> 2);
                int k = ks + (lane & 3);
                bh[nt][0] = Bh[k * BSTRIDE + n];
                bh[nt][1] = Bh[(k + 4) * BSTRIDE + n];
                bl[nt][0] = Bl[k * BSTRIDE + n];
                bl[nt][1] = Bl[(k + 4) * BSTRIDE + n];
            }
#pragma unroll
            for (int mt = 0; mt < 2; mt++)
#pragma unroll
                for (int nt = 0; nt < 8; nt++) {
                    mma_tf32(acc[mt][nt], ah[mt], bh[nt]);
                    mma_tf32(acc[mt][nt], ah[mt], bl[nt]);
                    mma_tf32(acc[mt][nt], al[mt], bh[nt]);
                }
        }
        __syncthreads();
    }

    // ---- epilogue ----
#pragma unroll
    for (int mt = 0; mt < 2; mt++) {
        int r0 = by * GBM + wm * 32 + mt * 16 + (lane >> 2);
#pragma unroll
        for (int nt = 0; nt < 8; nt++) {
            int c = bx * GBN + wn * 64 + nt * 8 + ((lane & 3) << 1);
            *(float2*)(C + (size_t)r0 * N + c) =
                make_float2(acc[mt][nt][0], acc[mt][nt][1]);
            *(float2*)(C + (size_t)(r0 + 8) * N + c) =
                make_float2(acc[mt][nt][2], acc[mt][nt][3]);
        }
    }
}

__global__ __launch_bounds__(256, 1) void proj_kernel(const float* __restrict__ x, W5 ws)
{
    const float* B = ws.w[blockIdx.z];
    float* C = g_P + (size_t)blockIdx.z * S_LEN * DMODEL;
    tf32_gemm_tile(x, B, C);
}

__global__ __launch_bounds__(256, 1) void out_gemm_kernel(const float* __restrict__ Wo,
                                                          float* __restrict__ out)
{
    tf32_gemm_tile(g_O, Wo, out);
}

// ---------------------------------------------------------------------------
// RoPE on Q (slot 0) and K (slot 1), in place.
// ---------------------------------------------------------------------------
__global__ __launch_bounds__(256) void rope_kernel(const float* __restrict__ cos_t,
                                                   const float* __restrict__ sin_t,
                                                   const int* __restrict__ pos)
{
    int idx = blockIdx.x * blockDim.x + threadIdx.x;
    int d = idx & 31;
    int h = (idx >> 5) & (NHEADS - 1);
    int s = idx >> 9;
    if (s >= S_LEN) return;
    int p = pos[s];

    float c0 = cos_t[p * HDIM + d];
    float c1 = cos_t[p * HDIM + d + 32];
    float s0 = sin_t[p * HDIM + d];
    float s1 = sin_t[p * HDIM + d + 32];

    float* base = g_P + (size_t)blockIdx.y * S_LEN * DMODEL + (size_t)s * DMODEL + h * HDIM;
    float x0 = base[d];
    float x1 = base[d + 32];
    base[d]      = x0 * c0 - x1 * s0;
    base[d + 32] = x1 * c1 + x0 * s1;
}

// ---------------------------------------------------------------------------
// Fused local (sliding-window + global boost) + global attention.
// One warp per (query i, head h), online softmax.
// ---------------------------------------------------------------------------
__global__ __launch_bounds__(128) void attn_kernel()
{
    int warp = (blockIdx.x * blockDim.x + threadIdx.x) >> 5;
    int lane = threadIdx.x & 31;
    int h = warp & (NHEADS - 1);
    int i = warp >> 4;
    if (i >= S_LEN) return;

    const float scale = 0.125f;
    const float* Q  = g_P;
    const float* K  = g_P + (size_t)1 * S_LEN * DMODEL;
    const float* V  = g_P + (size_t)2 * S_LEN * DMODEL;
    const float* KG = g_P + (size_t)3 * S_LEN * DMODEL;
    const float* VG = g_P + (size_t)4 * S_LEN * DMODEL;

    const float* qp = Q + (size_t)i * DMODEL + h * HDIM;
    float q0 = qp[lane], q1 = qp[lane + 32];

    int jlo = i - RADIUS; if (jlo < 0) jlo = 0;

    float m = -3.4e38f, sum = 0.f, a0 = 0.f, a1 = 0.f;

    for (int j = jlo; j <= i; j++) {
        const float* kp = K + (size_t)j * DMODEL + h * HDIM;
        float p = q0 * kp[lane] + q1 * kp[lane + 32];
#pragma unroll
        for (int o = 16; o > 0; o >>= 1) p += __shfl_xor_sync(0xffffffff, p, o);
        float s = p * scale;
        if (j < NGLOB) s += 1e9f;

        float mn = fmaxf(m, s);
        float esc = __expf(m - mn);
        float e = __expf(s - mn);
        const float* vp = V + (size_t)j * DMODEL + h * HDIM;
        sum = sum * esc + e;
        a0  = a0 * esc + e * vp[lane];
        a1  = a1 * esc + e * vp[lane + 32];
        m = mn;
    }
#pragma unroll
    for (int j = 0; j < NGLOB; j++) {
        if (j >= jlo && j <= i) continue;
        float s = 0.f;
        float mn = fmaxf(m, s);
        float esc = __expf(m - mn);
        float e = __expf(s - mn);
        const float* vp = V + (size_t)j * DMODEL + h * HDIM;
        sum = sum * esc + e;
        a0  = a0 * esc + e * vp[lane];
        a1  = a1 * esc + e * vp[lane + 32];
        m = mn;
    }
    float inv = 1.f / sum;
    float o0 = a0 * inv;
    float o1 = a1 * inv;

    float sg[NGLOB];
    float mg = -3.4e38f;
#pragma unroll
    for (int t = 0; t < NGLOB; t++) {
        const float* kp = KG + (size_t)t * DMODEL + h * HDIM;
        float p = q0 * kp[lane] + q1 * kp[lane + 32];
#pragma unroll
        for (int o = 16; o > 0; o >>= 1) p += __shfl_xor_sync(0xffffffff, p, o);
        sg[t] = p * scale;
        mg = fmaxf(mg, sg[t]);
    }
    float den = 0.f, gsum0 = 0.f, gsum1 = 0.f;
#pragma unroll
    for (int t = 0; t < NGLOB; t++) {
        float e = __expf(sg[t] - mg);
        const float* vp = VG + (size_t)t * DMODEL + h * HDIM;
        den += e;
        gsum0 += e * vp[lane];
        gsum1 += e * vp[lane + 32];
    }
    float ginv = 1.f / den;
    o0 += gsum0 * ginv;
    o1 += gsum1 * ginv;

    float* op = g_O + (size_t)i * DMODEL + h * HDIM;
    op[lane]      = o0;
    op[lane + 32] = o1;
}

// ---------------------------------------------------------------------------
// launch
// ---------------------------------------------------------------------------
extern "C" void kernel_launch(void* const* d_in, const int* in_sizes, int n_in,
                              void* d_out, int out_size)
{
    const float* x     = (const float*)d_in[0];
    const float* cos_t = (const float*)d_in[1];
    const float* sin_t = (const float*)d_in[2];
    const int*   pos   = (const int*)d_in[3];
    W5 ws;
    ws.w[0] = (const float*)d_in[4];   // Wqs -> Q
    ws.w[1] = (const float*)d_in[5];   // Wks -> K
    ws.w[2] = (const float*)d_in[6];   // Wvs -> V
    ws.w[3] = (const float*)d_in[8];   // Wkg -> KG   (d_in[7] = Wqg, unused)
    ws.w[4] = (const float*)d_in[9];   // Wvg -> VG
    const float* Wo = (const float*)d_in[10];
    float* out = (float*)d_out;

    dim3 gp(DMODEL / GBN, S_LEN / GBM, 5);
    proj_kernel<<<gp, 256>>>(x, ws);

    dim3 gr((S_LEN * NHEADS * 32) / 256, 2);
    rope_kernel<<<gr, 256>>>(cos_t, sin_t, pos);

    attn_kernel<<<(S_LEN * NHEADS) / 4, 128>>>();

    dim3 go(DMODEL / GBN, S_LEN / GBM);
    out_gemm_kernel<<<go, 256>>>(Wo, out);
}

// round 3
// speedup vs baseline: 1.3612x; 1.3541x over previous
#include <cuda_runtime.h>
#include <math.h>

#define S_LEN 2048
#define DMODEL 1024
#define NHEADS 16
#define HDIM 64
#define RADIUS 256
#define NGLOB 4

__device__ float g_P[(size_t)5 * S_LEN * DMODEL];
__device__ float g_O[(size_t)S_LEN * DMODEL];

struct W5 { const float* w[5]; };

__device__ __forceinline__ unsigned f2tf32(float x) {
    unsigned r;
    asm("cvt.rna.tf32.f32 %0, %1;" : "=r"(r) : "f"(x));
    return r;
}

__device__ __forceinline__ void mma_tf32(float* c, const unsigned* a, const unsigned* b) {
    asm volatile(
        "mma.sync.aligned.m16n8k8.row.col.f32.tf32.tf32.f32 "
        "{%0,%1,%2,%3}, {%4,%5,%6,%7}, {%8,%9}, {%0,%1,%2,%3};"
        : "+f"(c[0]), "+f"(c[1]), "+f"(c[2]), "+f"(c[3])
        : "r"(a[0]), "r"(a[1]), "r"(a[2]), "r"(a[3]), "r"(b[0]), "r"(b[1]));
}

// ---------------------------------------------------------------------------
// 3xTF32 GEMM (unchanged from round 2): 128x128x16, 8 warps, warp 32x64
// ---------------------------------------------------------------------------
#define GBM 128
#define GBN 128
#define GBK 16
#define ASTRIDE (GBK + 4)
#define BSTRIDE (GBN + 8)

__device__ __forceinline__ void tf32_gemm_tile(const float* __restrict__ A,
                                               const float* __restrict__ B,
                                               float* __restrict__ C)
{
    const int K = DMODEL, N = DMODEL;
    __shared__ unsigned Ah[GBM * ASTRIDE];
    __shared__ unsigned Al[GBM * ASTRIDE];
    __shared__ unsigned Bh[GBK * BSTRIDE];
    __shared__ unsigned Bl[GBK * BSTRIDE];

    int tid = threadIdx.x;
    int lane = tid & 31;
    int warp = tid >> 5;
    int wm = warp >> 1;
    int wn = warp & 1;
    int bx = blockIdx.x, by = blockIdx.y;

    float acc[2][8][4];
#pragma unroll
    for (int mt = 0; mt < 2; mt++)
#pragma unroll
        for (int nt = 0; nt < 8; nt++)
#pragma unroll
            for (int e = 0; e < 4; e++) acc[mt][nt][e] = 0.f;

    for (int k0 = 0; k0 < K; k0 += GBK) {
#pragma unroll
        for (int it = 0; it < 2; it++) {
            int l = tid + it * 256;
            int m = l >> 2;
            int kq = (l & 3) << 2;
            float4 v = *(const float4*)(A + (size_t)(by * GBM + m) * K + k0 + kq);
            float f[4] = {v.x, v.y, v.z, v.w};
#pragma unroll
            for (int e = 0; e < 4; e++) {
                unsigned h = f2tf32(f[e]);
                float lo = f[e] - __uint_as_float(h);
                Ah[m * ASTRIDE + kq + e] = h;
                Al[m * ASTRIDE + kq + e] = f2tf32(lo);
            }
        }
#pragma unroll
        for (int it = 0; it < 2; it++) {
            int l = tid + it * 256;
            int k = l >> 5;
            int nq = (l & 31) << 2;
            float4 v = *(const float4*)(B + (size_t)(k0 + k) * N + bx * GBN + nq);
            float f[4] = {v.x, v.y, v.z, v.w};
#pragma unroll
            for (int e = 0; e < 4; e++) {
                unsigned h = f2tf32(f[e]);
                float lo = f[e] - __uint_as_float(h);
                Bh[k * BSTRIDE + nq + e] = h;
                Bl[k * BSTRIDE + nq + e] = f2tf32(lo);
            }
        }
        __syncthreads();

#pragma unroll
        for (int ks = 0; ks < GBK; ks += 8) {
            unsigned ah[2][4], al[2][4], bh[8][2], bl[8][2];
#pragma unroll
            for (int mt = 0; mt < 2; mt++) {
                int r = wm * 32 + mt * 16 + (lane >> 2);
                int c = ks + (lane & 3);
                ah[mt][0] = Ah[r * ASTRIDE + c];
                ah[mt][1] = Ah[(r + 8) * ASTRIDE + c];
                ah[mt][2] = Ah[r * ASTRIDE + c + 4];
                ah[mt][3] = Ah[(r + 8) * ASTRIDE + c + 4];
                al[mt][0] = Al[r * ASTRIDE + c];
                al[mt][1] = Al[(r + 8) * ASTRIDE + c];
                al[mt][2] = Al[r * ASTRIDE + c + 4];
                al[mt][3] = Al[(r + 8) * ASTRIDE + c + 4];
            }
#pragma unroll
            for (int nt = 0; nt < 8; nt++) {
                int n = wn * 64 + nt * 8 + (lane >> 2);
                int k = ks + (lane & 3);
                bh[nt][0] = Bh[k * BSTRIDE + n];
                bh[nt][1] = Bh[(k + 4) * BSTRIDE + n];
                bl[nt][0] = Bl[k * BSTRIDE + n];
                bl[nt][1] = Bl[(k + 4) * BSTRIDE + n];
            }
#pragma unroll
            for (int mt = 0; mt < 2; mt++)
#pragma unroll
                for (int nt = 0; nt < 8; nt++) {
                    mma_tf32(acc[mt][nt], ah[mt], bh[nt]);
                    mma_tf32(acc[mt][nt], ah[mt], bl[nt]);
                    mma_tf32(acc[mt][nt], al[mt], bh[nt]);
                }
        }
        __syncthreads();
    }

#pragma unroll
    for (int mt = 0; mt < 2; mt++) {
        int r0 = by * GBM + wm * 32 + mt * 16 + (lane >> 2);
#pragma unroll
        for (int nt = 0; nt < 8; nt++) {
            int c = bx * GBN + wn * 64 + nt * 8 + ((lane & 3) << 1);
            *(float2*)(C + (size_t)r0 * N + c) =
                make_float2(acc[mt][nt][0], acc[mt][nt][1]);
            *(float2*)(C + (size_t)(r0 + 8) * N + c) =
                make_float2(acc[mt][nt][2], acc[mt][nt][3]);
        }
    }
}

__global__ __launch_bounds__(256, 1) void proj_kernel(const float* __restrict__ x, W5 ws)
{
    const float* B = ws.w[blockIdx.z];
    float* C = g_P + (size_t)blockIdx.z * S_LEN * DMODEL;
    tf32_gemm_tile(x, B, C);
}

__global__ __launch_bounds__(256, 1) void out_gemm_kernel(const float* __restrict__ Wo,
                                                          float* __restrict__ out)
{
    tf32_gemm_tile(g_O, Wo, out);
}

// ---------------------------------------------------------------------------
// RoPE on Q (slot 0) and K (slot 1), in place.
// ---------------------------------------------------------------------------
__global__ __launch_bounds__(256) void rope_kernel(const float* __restrict__ cos_t,
                                                   const float* __restrict__ sin_t,
                                                   const int* __restrict__ pos)
{
    int idx = blockIdx.x * blockDim.x + threadIdx.x;
    int d = idx & 31;
    int h = (idx >> 5) & (NHEADS - 1);
    int s = idx >> 9;
    if (s >= S_LEN) return;
    int p = pos[s];

    float c0 = cos_t[p * HDIM + d];
    float c1 = cos_t[p * HDIM + d + 32];
    float s0 = sin_t[p * HDIM + d];
    float s1 = sin_t[p * HDIM + d + 32];

    float* base = g_P + (size_t)blockIdx.y * S_LEN * DMODEL + (size_t)s * DMODEL + h * HDIM;
    float x0 = base[d];
    float x1 = base[d + 32];
    base[d]      = x0 * c0 - x1 * s0;
    base[d + 32] = x1 * c1 + x0 * s1;
}

// ---------------------------------------------------------------------------
// Block-tiled MMA flash attention (local window + exact global-boost semantics)
// block = (head h, 64-query tile), 128 threads = 4 warps, warp = 16 q rows.
// ---------------------------------------------------------------------------
#define KSTR 68
#define VSTR 72
#define PSTR 68
// dynamic smem layout (uint words)
#define OFF_KH 0
#define OFF_KL (OFF_KH + 64 * KSTR)
#define OFF_VH (OFF_KL + 64 * KSTR)
#define OFF_VL (OFF_VH + 64 * VSTR)
#define OFF_PH (OFF_VL + 64 * VSTR)
#define OFF_PL (OFF_PH + 64 * PSTR)
#define OFF_VG (OFF_PL + 64 * PSTR)
#define ATT_SMEM_WORDS (OFF_VG + HDIM)

__global__ __launch_bounds__(128, 2) void attn_kernel()
{
    extern __shared__ unsigned smem_u[];
    unsigned* Kh = smem_u + OFF_KH;
    unsigned* Kl = smem_u + OFF_KL;
    unsigned* Vh = smem_u + OFF_VH;
    unsigned* Vl = smem_u + OFF_VL;
    unsigned* Ph = smem_u + OFF_PH;
    unsigned* Pl = smem_u + OFF_PL;
    float*    Vg4 = (float*)(smem_u + OFF_VG);

    const int h  = blockIdx.x;
    const int i0 = blockIdx.y * 64;
    const int tid = threadIdx.x;
    const int lane = tid & 31;
    const int wq = tid >> 5;              // warp 0..3 -> q rows wq*16..+16

    const float* Q = g_P;
    const float* K = g_P + (size_t)1 * S_LEN * DMODEL;
    const float* V = g_P + (size_t)2 * S_LEN * DMODEL;

    // ---- precompute sum of V rows 0..3 (for pseudo global chunk) ----
    if (tid < HDIM) {
        const float* vb = V + h * HDIM + tid;
        Vg4[tid] = vb[0] + vb[DMODEL] + vb[2 * DMODEL] + vb[3 * DMODEL];
    }

    // ---- load Q A-fragments (hi/lo), kept in regs for all chunks ----
    unsigned qh[8][4], ql[8][4];
    {
        const int r0 = i0 + wq * 16 + (lane >> 2);
#pragma unroll
        for (int ks = 0; ks < 8; ks++) {
            int c = h * HDIM + ks * 8 + (lane & 3);
            float f[4];
            f[0] = Q[(size_t)r0 * DMODEL + c];
            f[1] = Q[(size_t)(r0 + 8) * DMODEL + c];
            f[2] = Q[(size_t)r0 * DMODEL + c + 4];
            f[3] = Q[(size_t)(r0 + 8) * DMODEL + c + 4];
#pragma unroll
            for (int e = 0; e < 4; e++) {
                unsigned hi = f2tf32(f[e]);
                qh[ks][e] = hi;
                ql[ks][e] = f2tf32(f[e] - __uint_as_float(hi));
            }
        }
    }

    float out[8][4];
#pragma unroll
    for (int nt = 0; nt < 8; nt++)
#pragma unroll
        for (int e = 0; e < 4; e++) out[nt][e] = 0.f;
    float m0 = -3.4e38f, m1 = -3.4e38f, sum0 = 0.f, sum1 = 0.f;

    const int j_start = (i0 - RADIUS) > 0 ? (i0 - RADIUS) : 0;

    for (int jc = j_start; jc < i0 + 64; jc += 64) {
        __syncthreads();   // protect K/V buffers (and Vg4 on first iter)
        // ---- stage K,V chunk [64 keys x 64 dims] hi/lo ----
#pragma unroll
        for (int it = 0; it < 8; it++) {
            int idx = it * 128 + tid;          // 1024 float4 slots
            int key = idx >> 4;
            int dq = (idx & 15) << 2;
            size_t gofs = (size_t)(jc + key) * DMODEL + h * HDIM + dq;
            float4 kv = *(const float4*)(K + gofs);
            float4 vv = *(const float4*)(V + gofs);
            float kf[4] = {kv.x, kv.y, kv.z, kv.w};
            float vf[4] = {vv.x, vv.y, vv.z, vv.w};
#pragma unroll
            for (int e = 0; e < 4; e++) {
                unsigned hk = f2tf32(kf[e]);
                Kh[key * KSTR + dq + e] = hk;
                Kl[key * KSTR + dq + e] = f2tf32(kf[e] - __uint_as_float(hk));
                unsigned hv = f2tf32(vf[e]);
                Vh[key * VSTR + dq + e] = hv;
                Vl[key * VSTR + dq + e] = f2tf32(vf[e] - __uint_as_float(hv));
            }
        }
        __syncthreads();

        // ---- scores: S[16 x 64] = Q_frag x K_chunk (3xTF32) ----
        float sc[8][4];
#pragma unroll
        for (int nt = 0; nt < 8; nt++)
#pragma unroll
            for (int e = 0; e < 4; e++) sc[nt][e] = 0.f;

#pragma unroll
        for (int ks = 0; ks < 8; ks++) {
#pragma unroll
            for (int nt = 0; nt < 8; nt++) {
                int n = nt * 8 + (lane >> 2);
                int k = ks * 8 + (lane & 3);
                unsigned bh[2], bl[2];
                bh[0] = Kh[n * KSTR + k];
                bh[1] = Kh[n * KSTR + k + 4];
                bl[0] = Kl[n * KSTR + k];
                bl[1] = Kl[n * KSTR + k + 4];
                mma_tf32(sc[nt], qh[ks], bh);
                mma_tf32(sc[nt], qh[ks], bl);
                mma_tf32(sc[nt], ql[ks], bh);
            }
        }

        // ---- mask + exact reference semantics ----
        const int ibase = i0 + wq * 16 + (lane >> 2);
        float mn0 = m0, mn1 = m1;
#pragma unroll
        for (int nt = 0; nt < 8; nt++) {
#pragma unroll
            for (int e = 0; e < 4; e++) {
                int i = ibase + ((e & 2) ? 8 : 0);
                int j = jc + nt * 8 + 2 * (lane & 3) + (e & 1);
                bool inw = (j <= i) && (i - j <= RADIUS);
                float raw = sc[nt][e] * 0.125f;
                float s;
                if (j < NGLOB) s = inw ? (raw + 1e9f) : 0.f;
                else           s = inw ? raw : -3.0e38f;
                sc[nt][e] = s;
                if (e & 2) mn1 = fmaxf(mn1, s); else mn0 = fmaxf(mn0, s);
            }
        }
        // quad reduce row max
#pragma unroll
        for (int o = 1; o < 4; o <<= 1) {
            mn0 = fmaxf(mn0, __shfl_xor_sync(0xffffffff, mn0, o));
            mn1 = fmaxf(mn1, __shfl_xor_sync(0xffffffff, mn1, o));
        }
        float esc0 = __expf(m0 - mn0);
        float esc1 = __expf(m1 - mn1);
        m0 = mn0; m1 = mn1;

        float ps0 = 0.f, ps1 = 0.f;
#pragma unroll
        for (int nt = 0; nt < 8; nt++) {
#pragma unroll
            for (int e = 0; e < 4; e++) {
                float p = __expf(sc[nt][e] - ((e & 2) ? m1 : m0));
                sc[nt][e] = p;
                if (e & 2) ps1 += p; else ps0 += p;
            }
        }
#pragma unroll
        for (int o = 1; o < 4; o <<= 1) {
            ps0 += __shfl_xor_sync(0xffffffff, ps0, o);
            ps1 += __shfl_xor_sync(0xffffffff, ps1, o);
        }
        sum0 = sum0 * esc0 + ps0;
        sum1 = sum1 * esc1 + ps1;
#pragma unroll
        for (int nt = 0; nt < 8; nt++) {
            out[nt][0] *= esc0; out[nt][1] *= esc0;
            out[nt][2] *= esc1; out[nt][3] *= esc1;
        }

        // ---- write P (hi/lo) to warp-private smem rows ----
#pragma unroll
        for (int nt = 0; nt < 8; nt++) {
#pragma unroll
            for (int e = 0; e < 4; e++) {
                int row = wq * 16 + (lane >> 2) + ((e & 2) ? 8 : 0);
                int col = nt * 8 + 2 * (lane & 3) + (e & 1);
                float p = sc[nt][e];
                unsigned hp = f2tf32(p);
                Ph[row * PSTR + col] = hp;
                Pl[row * PSTR + col] = f2tf32(p - __uint_as_float(hp));
            }
        }
        __syncwarp();

        // ---- out += P[16x64] x V[64x64] (3xTF32) ----
#pragma unroll
        for (int ks = 0; ks < 8; ks++) {
            int r = wq * 16 + (lane >> 2);
            int c = ks * 8 + (lane & 3);
            unsigned pah[4], pal[4];
            pah[0] = Ph[r * PSTR + c];
            pah[1] = Ph[(r + 8) * PSTR + c];
            pah[2] = Ph[r * PSTR + c + 4];
            pah[3] = Ph[(r + 8) * PSTR + c + 4];
            pal[0] = Pl[r * PSTR + c];
            pal[1] = Pl[(r + 8) * PSTR + c];
            pal[2] = Pl[r * PSTR + c + 4];
            pal[3] = Pl[(r + 8) * PSTR + c + 4];
#pragma unroll
            for (int nt = 0; nt < 8; nt++) {
                int k = ks * 8 + (lane & 3);
                int n = nt * 8 + (lane >> 2);
                unsigned vbh[2], vbl[2];
                vbh[0] = Vh[k * VSTR + n];
                vbh[1] = Vh[(k + 4) * VSTR + n];
                vbl[0] = Vl[k * VSTR + n];
                vbl[1] = Vl[(k + 4) * VSTR + n];
                mma_tf32(out[nt], pah, vbh);
                mma_tf32(out[nt], pah, vbl);
                mma_tf32(out[nt], pal, vbh);
            }
        }
        __syncwarp();
    }

    // ---- pseudo-chunk: global cols 0..3 (score exactly 0) when not covered ----
    if (j_start > 0) {
        float mn0 = fmaxf(m0, 0.f), mn1 = fmaxf(m1, 0.f);
        float esc0 = __expf(m0 - mn0), esc1 = __expf(m1 - mn1);
        float e0 = __expf(0.f - mn0), e1 = __expf(0.f - mn1);
        sum0 = sum0 * esc0 + 4.f * e0;
        sum1 = sum1 * esc1 + 4.f * e1;
#pragma unroll
        for (int nt = 0; nt < 8; nt++) {
            int col = nt * 8 + 2 * (lane & 3);
            out[nt][0] = out[nt][0] * esc0 + e0 * Vg4[col];
            out[nt][1] = out[nt][1] * esc0 + e0 * Vg4[col + 1];
            out[nt][2] = out[nt][2] * esc1 + e1 * Vg4[col];
            out[nt][3] = out[nt][3] * esc1 + e1 * Vg4[col + 1];
        }
    }

    // ---- normalize + store ----
    float inv0 = 1.f / sum0, inv1 = 1.f / sum1;
    const int r0 = i0 + wq * 16 + (lane >> 2);
#pragma unroll
    for (int nt = 0; nt < 8; nt++) {
        int cb = h * HDIM + nt * 8 + 2 * (lane & 3);
        *(float2*)(g_O + (size_t)r0 * DMODEL + cb) =
            make_float2(out[nt][0] * inv0, out[nt][1] * inv0);
        *(float2*)(g_O + (size_t)(r0 + 8) * DMODEL + cb) =
            make_float2(out[nt][2] * inv1, out[nt][3] * inv1);
    }
}

// ---------------------------------------------------------------------------
// Global attention (KG/VG, 4 columns) — adds into g_O. Warp per (i, h).
// ---------------------------------------------------------------------------
__global__ __launch_bounds__(128) void global_attn_kernel()
{
    int warp = (blockIdx.x * blockDim.x + threadIdx.x) >> 5;
    int lane = threadIdx.x & 31;
    int h = warp & (NHEADS - 1);
    int i = warp >> 4;
    if (i >= S_LEN) return;

    const float scale = 0.125f;
    const float* Q  = g_P;
    const float* KG = g_P + (size_t)3 * S_LEN * DMODEL;
    const float* VG = g_P + (size_t)4 * S_LEN * DMODEL;

    const float* qp = Q + (size_t)i * DMODEL + h * HDIM;
    float q0 = qp[lane], q1 = qp[lane + 32];

    float sg[NGLOB];
    float mg = -3.4e38f;
#pragma unroll
    for (int t = 0; t < NGLOB; t++) {
        const float* kp = KG + (size_t)t * DMODEL + h * HDIM;
        float p = q0 * kp[lane] + q1 * kp[lane + 32];
#pragma unroll
        for (int o = 16; o > 0; o >>= 1) p += __shfl_xor_sync(0xffffffff, p, o);
        sg[t] = p * scale;
        mg = fmaxf(mg, sg[t]);
    }
    float den = 0.f, gsum0 = 0.f, gsum1 = 0.f;
#pragma unroll
    for (int t = 0; t < NGLOB; t++) {
        float e = __expf(sg[t] - mg);
        const float* vp = VG + (size_t)t * DMODEL + h * HDIM;
        den += e;
        gsum0 += e * vp[lane];
        gsum1 += e * vp[lane + 32];
    }
    float ginv = 1.f / den;

    float* op = g_O + (size_t)i * DMODEL + h * HDIM;
    op[lane]      += gsum0 * ginv;
    op[lane + 32] += gsum1 * ginv;
}

// ---------------------------------------------------------------------------
// launch
// ---------------------------------------------------------------------------
extern "C" void kernel_launch(void* const* d_in, const int* in_sizes, int n_in,
                              void* d_out, int out_size)
{
    const float* x     = (const float*)d_in[0];
    const float* cos_t = (const float*)d_in[1];
    const float* sin_t = (const float*)d_in[2];
    const int*   pos   = (const int*)d_in[3];
    W5 ws;
    ws.w[0] = (const float*)d_in[4];   // Wqs -> Q
    ws.w[1] = (const float*)d_in[5];   // Wks -> K
    ws.w[2] = (const float*)d_in[6];   // Wvs -> V
    ws.w[3] = (const float*)d_in[8];   // Wkg -> KG   (d_in[7] = Wqg, unused)
    ws.w[4] = (const float*)d_in[9];   // Wvg -> VG
    const float* Wo = (const float*)d_in[10];
    float* out = (float*)d_out;

    static int smem_set = 0;
    int attn_smem = ATT_SMEM_WORDS * 4;
    if (!smem_set) {
        cudaFuncSetAttribute(attn_kernel,
                             cudaFuncAttributeMaxDynamicSharedMemorySize, attn_smem);
        smem_set = 1;
    }

    dim3 gp(DMODEL / GBN, S_LEN / GBM, 5);
    proj_kernel<<<gp, 256>>>(x, ws);

    dim3 gr((S_LEN * NHEADS * 32) / 256, 2);
    rope_kernel<<<gr, 256>>>(cos_t, sin_t, pos);

    dim3 ga(NHEADS, S_LEN / 64);
    attn_kernel<<<ga, 128, attn_smem>>>();

    global_attn_kernel<<<(S_LEN * NHEADS) / 4, 128>>>();

    dim3 go(DMODEL / GBN, S_LEN / GBM);
    out_gemm_kernel<<<go, 256>>>(Wo, out);
}

// round 4
// speedup vs baseline: 1.9801x; 1.4547x over previous
#include <cuda_runtime.h>
#include <math.h>

#define S_LEN 2048
#define DMODEL 1024
#define NHEADS 16
#define HDIM 64
#define RADIUS 256
#define NGLOB 4

__device__ float g_P[(size_t)5 * S_LEN * DMODEL];
__device__ float g_O[(size_t)S_LEN * DMODEL];

// pre-split tf32 hi/lo buffers: [0 : 2M) activations, [2M + z*1M) weights z=0..5
#define ACT_ELEMS (S_LEN * DMODEL)
#define W_ELEMS   (DMODEL * DMODEL)
__device__ unsigned g_Sh[(size_t)ACT_ELEMS + 6 * W_ELEMS];
__device__ unsigned g_Sl[(size_t)ACT_ELEMS + 6 * W_ELEMS];

__device__ __forceinline__ unsigned f2tf32(float x) {
    unsigned r;
    asm("cvt.rna.tf32.f32 %0, %1;" : "=r"(r) : "f"(x));
    return r;
}

__device__ __forceinline__ void mma_tf32(float* c, const unsigned* a, const unsigned* b) {
    asm volatile(
        "mma.sync.aligned.m16n8k8.row.col.f32.tf32.tf32.f32 "
        "{%0,%1,%2,%3}, {%4,%5,%6,%7}, {%8,%9}, {%0,%1,%2,%3};"
        : "+f"(c[0]), "+f"(c[1]), "+f"(c[2]), "+f"(c[3])
        : "r"(a[0]), "r"(a[1]), "r"(a[2]), "r"(a[3]), "r"(b[0]), "r"(b[1]));
}

__device__ __forceinline__ void cpa16(unsigned* dst, const unsigned* src) {
    unsigned s = (unsigned)__cvta_generic_to_shared(dst);
    asm volatile("cp.async.cg.shared.global [%0], [%1], 16;" :: "r"(s), "l"(src));
}

// ---------------------------------------------------------------------------
// split kernel: src fp32 -> (tf32 hi, tf32 lo) bit patterns
// ---------------------------------------------------------------------------
__global__ __launch_bounds__(256) void split_kernel(const float* __restrict__ src,
                                                    unsigned* __restrict__ h,
                                                    unsigned* __restrict__ l, int n4)
{
    int i = blockIdx.x * blockDim.x + threadIdx.x;
    if (i >= n4) return;
    float4 v = ((const float4*)src)[i];
    float f[4] = {v.x, v.y, v.z, v.w};
    uint4 hv, lv;
    unsigned* hp = &hv.x;
    unsigned* lp = &lv.x;
#pragma unroll
    for (int e = 0; e < 4; e++) {
        unsigned hb = f2tf32(f[e]);
        hp[e] = hb;
        lp[e] = f2tf32(f[e] - __uint_as_float(hb));
    }
    ((uint4*)h)[i] = hv;
    ((uint4*)l)[i] = lv;
}

// ---------------------------------------------------------------------------
// 3xTF32 GEMM, pre-split inputs, 3-stage cp.async pipeline.
// block 128x128x16, 8 warps (4M x 2N), warp tile 32x64
// ---------------------------------------------------------------------------
#define GBK 16
#define ASTRIDE 20          // 128 x 20 words per A stage
#define BSTRIDE 136         // 16 x 136 words per B stage
#define SA_WORDS (128 * ASTRIDE)
#define SB_WORDS (GBK * BSTRIDE)
#define GEMM_SMEM_WORDS (3 * 2 * (SA_WORDS + SB_WORDS))
#define GEMM_SMEM_BYTES (GEMM_SMEM_WORDS * 4)

__device__ __forceinline__ void gemm3_body(const unsigned* __restrict__ Agh,
                                           const unsigned* __restrict__ Agl,
                                           const unsigned* __restrict__ Bgh,
                                           const unsigned* __restrict__ Bgl,
                                           float* __restrict__ C)
{
    extern __shared__ unsigned sm[];
    unsigned* uAh = sm;
    unsigned* uAl = sm + 3 * SA_WORDS;
    unsigned* uBh = sm + 6 * SA_WORDS;
    unsigned* uBl = uBh + 3 * SB_WORDS;

    const int tid = threadIdx.x;
    const int lane = tid & 31;
    const int warp = tid >> 5;
    const int wm = warp >> 1;
    const int wn = warp & 1;
    const int bx = blockIdx.x, by = blockIdx.y;

    float acc[2][8][4];
#pragma unroll
    for (int mt = 0; mt < 2; mt++)
#pragma unroll
        for (int nt = 0; nt < 8; nt++)
#pragma unroll
            for (int e = 0; e < 4; e++) acc[mt][nt][e] = 0.f;

    // stage loader
    auto load_stage = [&](int st, int k0) {
        unsigned* ah = uAh + st * SA_WORDS;
        unsigned* al = uAl + st * SA_WORDS;
        unsigned* bh = uBh + st * SB_WORDS;
        unsigned* bl = uBl + st * SB_WORDS;
#pragma unroll
        for (int it = 0; it < 2; it++) {
            int idx = tid + it * 256;
            int m = idx >> 2, kq = (idx & 3) << 2;
            size_t ga = (size_t)(by * 128 + m) * DMODEL + k0 + kq;
            cpa16(ah + m * ASTRIDE + kq, Agh + ga);
            cpa16(al + m * ASTRIDE + kq, Agl + ga);
            int kk = idx >> 5, nq = (idx & 31) << 2;
            size_t gb = (size_t)(k0 + kk) * DMODEL + bx * 128 + nq;
            cpa16(bh + kk * BSTRIDE + nq, Bgh + gb);
            cpa16(bl + kk * BSTRIDE + nq, Bgl + gb);
        }
    };

    load_stage(0, 0);
    asm volatile("cp.async.commit_group;");
    load_stage(1, GBK);
    asm volatile("cp.async.commit_group;");

    const int NT = DMODEL / GBK;   // 64
#pragma unroll 1
    for (int i = 0; i < NT; i++) {
        int st = i % 3;
        asm volatile("cp.async.wait_group 1;");
        __syncthreads();

        unsigned* ah_s = uAh + st * SA_WORDS;
        unsigned* al_s = uAl + st * SA_WORDS;
        unsigned* bh_s = uBh + st * SB_WORDS;
        unsigned* bl_s = uBl + st * SB_WORDS;

#pragma unroll
        for (int ks = 0; ks < GBK; ks += 8) {
            unsigned ah[2][4], al[2][4];
#pragma unroll
            for (int mt = 0; mt < 2; mt++) {
                int r = wm * 32 + mt * 16 + (lane >> 2);
                int c = ks + (lane & 3);
                ah[mt][0] = ah_s[r * ASTRIDE + c];
                ah[mt][1] = ah_s[(r + 8) * ASTRIDE + c];
                ah[mt][2] = ah_s[r * ASTRIDE + c + 4];
                ah[mt][3] = ah_s[(r + 8) * ASTRIDE + c + 4];
                al[mt][0] = al_s[r * ASTRIDE + c];
                al[mt][1] = al_s[(r + 8) * ASTRIDE + c];
                al[mt][2] = al_s[r * ASTRIDE + c + 4];
                al[mt][3] = al_s[(r + 8) * ASTRIDE + c + 4];
            }
#pragma unroll
            for (int nt = 0; nt < 8; nt++) {
                int n = wn * 64 + nt * 8 + (lane >> 2);
                int k = ks + (lane & 3);
                unsigned bh[2], bl[2];
                bh[0] = bh_s[k * BSTRIDE + n];
                bh[1] = bh_s[(k + 4) * BSTRIDE + n];
                bl[0] = bl_s[k * BSTRIDE + n];
                bl[1] = bl_s[(k + 4) * BSTRIDE + n];
#pragma unroll
                for (int mt = 0; mt < 2; mt++) {
                    mma_tf32(acc[mt][nt], ah[mt], bh);
                    mma_tf32(acc[mt][nt], ah[mt], bl);
                    mma_tf32(acc[mt][nt], al[mt], bh);
                }
            }
        }

        if (i + 2 < NT) load_stage((i + 2) % 3, (i + 2) * GBK);
        asm volatile("cp.async.commit_group;");
    }

#pragma unroll
    for (int mt = 0; mt < 2; mt++) {
        int r0 = by * 128 + wm * 32 + mt * 16 + (lane >> 2);
#pragma unroll
        for (int nt = 0; nt < 8; nt++) {
            int c = bx * 128 + wn * 64 + nt * 8 + ((lane & 3) << 1);
            *(float2*)(C + (size_t)r0 * DMODEL + c) =
                make_float2(acc[mt][nt][0], acc[mt][nt][1]);
            *(float2*)(C + (size_t)(r0 + 8) * DMODEL + c) =
                make_float2(acc[mt][nt][2], acc[mt][nt][3]);
        }
    }
}

__global__ __launch_bounds__(256, 1) void proj_kernel()
{
    int z = blockIdx.z;
    gemm3_body(g_Sh, g_Sl,
               g_Sh + ACT_ELEMS + (size_t)z * W_ELEMS,
               g_Sl + ACT_ELEMS + (size_t)z * W_ELEMS,
               g_P + (size_t)z * ACT_ELEMS);
}

__global__ __launch_bounds__(256, 1) void out_gemm_kernel(float* __restrict__ out)
{
    gemm3_body(g_Sh, g_Sl,
               g_Sh + ACT_ELEMS + (size_t)5 * W_ELEMS,
               g_Sl + ACT_ELEMS + (size_t)5 * W_ELEMS,
               out);
}

// ---------------------------------------------------------------------------
// RoPE on Q (slot 0) and K (slot 1), in place.
// ---------------------------------------------------------------------------
__global__ __launch_bounds__(256) void rope_kernel(const float* __restrict__ cos_t,
                                                   const float* __restrict__ sin_t,
                                                   const int* __restrict__ pos)
{
    int idx = blockIdx.x * blockDim.x + threadIdx.x;
    int d = idx & 31;
    int h = (idx >> 5) & (NHEADS - 1);
    int s = idx >> 9;
    if (s >= S_LEN) return;
    int p = pos[s];

    float c0 = cos_t[p * HDIM + d];
    float c1 = cos_t[p * HDIM + d + 32];
    float s0 = sin_t[p * HDIM + d];
    float s1 = sin_t[p * HDIM + d + 32];

    float* base = g_P + (size_t)blockIdx.y * ACT_ELEMS + (size_t)s * DMODEL + h * HDIM;
    float x0 = base[d];
    float x1 = base[d + 32];
    base[d]      = x0 * c0 - x1 * s0;
    base[d + 32] = x1 * c1 + x0 * s1;
}

// ---------------------------------------------------------------------------
// Block-tiled MMA flash attention (unchanged from round 3)
// ---------------------------------------------------------------------------
#define KSTR 68
#define VSTR 72
#define PSTR 68
#define OFF_KH 0
#define OFF_KL (OFF_KH + 64 * KSTR)
#define OFF_VH (OFF_KL + 64 * KSTR)
#define OFF_VL (OFF_VH + 64 * VSTR)
#define OFF_PH (OFF_VL + 64 * VSTR)
#define OFF_PL (OFF_PH + 64 * PSTR)
#define OFF_VG (OFF_PL + 64 * PSTR)
#define ATT_SMEM_WORDS (OFF_VG + HDIM)

__global__ __launch_bounds__(128, 2) void attn_kernel()
{
    extern __shared__ unsigned smem_u[];
    unsigned* Kh = smem_u + OFF_KH;
    unsigned* Kl = smem_u + OFF_KL;
    unsigned* Vh = smem_u + OFF_VH;
    unsigned* Vl = smem_u + OFF_VL;
    unsigned* Ph = smem_u + OFF_PH;
    unsigned* Pl = smem_u + OFF_PL;
    float*    Vg4 = (float*)(smem_u + OFF_VG);

    const int h  = blockIdx.x;
    const int i0 = blockIdx.y * 64;
    const int tid = threadIdx.x;
    const int lane = tid & 31;
    const int wq = tid >> 5;

    const float* Q = g_P;
    const float* K = g_P + (size_t)1 * ACT_ELEMS;
    const float* V = g_P + (size_t)2 * ACT_ELEMS;

    if (tid < HDIM) {
        const float* vb = V + h * HDIM + tid;
        Vg4[tid] = vb[0] + vb[DMODEL] + vb[2 * DMODEL] + vb[3 * DMODEL];
    }

    unsigned qh[8][4], ql[8][4];
    {
        const int r0 = i0 + wq * 16 + (lane >> 2);
#pragma unroll
        for (int ks = 0; ks < 8; ks++) {
            int c = h * HDIM + ks * 8 + (lane & 3);
            float f[4];
            f[0] = Q[(size_t)r0 * DMODEL + c];
            f[1] = Q[(size_t)(r0 + 8) * DMODEL + c];
            f[2] = Q[(size_t)r0 * DMODEL + c + 4];
            f[3] = Q[(size_t)(r0 + 8) * DMODEL + c + 4];
#pragma unroll
            for (int e = 0; e < 4; e++) {
                unsigned hi = f2tf32(f[e]);
                qh[ks][e] = hi;
                ql[ks][e] = f2tf32(f[e] - __uint_as_float(hi));
            }
        }
    }

    float out[8][4];
#pragma unroll
    for (int nt = 0; nt < 8; nt++)
#pragma unroll
        for (int e = 0; e < 4; e++) out[nt][e] = 0.f;
    float m0 = -3.4e38f, m1 = -3.4e38f, sum0 = 0.f, sum1 = 0.f;

    const int j_start = (i0 - RADIUS) > 0 ? (i0 - RADIUS) : 0;

    for (int jc = j_start; jc < i0 + 64; jc += 64) {
        __syncthreads();
#pragma unroll
        for (int it = 0; it < 8; it++) {
            int idx = it * 128 + tid;
            int key = idx >> 4;
            int dq = (idx & 15) << 2;
            size_t gofs = (size_t)(jc + key) * DMODEL + h * HDIM + dq;
            float4 kv = *(const float4*)(K + gofs);
            float4 vv = *(const float4*)(V + gofs);
            float kf[4] = {kv.x, kv.y, kv.z, kv.w};
            float vf[4] = {vv.x, vv.y, vv.z, vv.w};
#pragma unroll
            for (int e = 0; e < 4; e++) {
                unsigned hk = f2tf32(kf[e]);
                Kh[key * KSTR + dq + e] = hk;
                Kl[key * KSTR + dq + e] = f2tf32(kf[e] - __uint_as_float(hk));
                unsigned hv = f2tf32(vf[e]);
                Vh[key * VSTR + dq + e] = hv;
                Vl[key * VSTR + dq + e] = f2tf32(vf[e] - __uint_as_float(hv));
            }
        }
        __syncthreads();

        float sc[8][4];
#pragma unroll
        for (int nt = 0; nt < 8; nt++)
#pragma unroll
            for (int e = 0; e < 4; e++) sc[nt][e] = 0.f;

#pragma unroll
        for (int ks = 0; ks < 8; ks++) {
#pragma unroll
            for (int nt = 0; nt < 8; nt++) {
                int n = nt * 8 + (lane >> 2);
                int k = ks * 8 + (lane & 3);
                unsigned bh[2], bl[2];
                bh[0] = Kh[n * KSTR + k];
                bh[1] = Kh[n * KSTR + k + 4];
                bl[0] = Kl[n * KSTR + k];
                bl[1] = Kl[n * KSTR + k + 4];
                mma_tf32(sc[nt], qh[ks], bh);
                mma_tf32(sc[nt], qh[ks], bl);
                mma_tf32(sc[nt], ql[ks], bh);
            }
        }

        const int ibase = i0 + wq * 16 + (lane >> 2);
        float mn0 = m0, mn1 = m1;
#pragma unroll
        for (int nt = 0; nt < 8; nt++) {
#pragma unroll
            for (int e = 0; e < 4; e++) {
                int i = ibase + ((e & 2) ? 8 : 0);
                int j = jc + nt * 8 + 2 * (lane & 3) + (e & 1);
                bool inw = (j <= i) && (i - j <= RADIUS);
                float raw = sc[nt][e] * 0.125f;
                float s;
                if (j < NGLOB) s = inw ? (raw + 1e9f) : 0.f;
                else           s = inw ? raw : -3.0e38f;
                sc[nt][e] = s;
                if (e & 2) mn1 = fmaxf(mn1, s); else mn0 = fmaxf(mn0, s);
            }
        }
#pragma unroll
        for (int o = 1; o < 4; o <<= 1) {
            mn0 = fmaxf(mn0, __shfl_xor_sync(0xffffffff, mn0, o));
            mn1 = fmaxf(mn1, __shfl_xor_sync(0xffffffff, mn1, o));
        }
        float esc0 = __expf(m0 - mn0);
        float esc1 = __expf(m1 - mn1);
        m0 = mn0; m1 = mn1;

        float ps0 = 0.f, ps1 = 0.f;
#pragma unroll
        for (int nt = 0; nt < 8; nt++) {
#pragma unroll
            for (int e = 0; e < 4; e++) {
                float p = __expf(sc[nt][e] - ((e & 2) ? m1 : m0));
                sc[nt][e] = p;
                if (e & 2) ps1 += p; else ps0 += p;
            }
        }
#pragma unroll
        for (int o = 1; o < 4; o <<= 1) {
            ps0 += __shfl_xor_sync(0xffffffff, ps0, o);
            ps1 += __shfl_xor_sync(0xffffffff, ps1, o);
        }
        sum0 = sum0 * esc0 + ps0;
        sum1 = sum1 * esc1 + ps1;
#pragma unroll
        for (int nt = 0; nt < 8; nt++) {
            out[nt][0] *= esc0; out[nt][1] *= esc0;
            out[nt][2] *= esc1; out[nt][3] *= esc1;
        }

#pragma unroll
        for (int nt = 0; nt < 8; nt++) {
#pragma unroll
            for (int e = 0; e < 4; e++) {
                int row = wq * 16 + (lane >> 2) + ((e & 2) ? 8 : 0);
                int col = nt * 8 + 2 * (lane & 3) + (e & 1);
                float p = sc[nt][e];
                unsigned hp = f2tf32(p);
                Ph[row * PSTR + col] = hp;
                Pl[row * PSTR + col] = f2tf32(p - __uint_as_float(hp));
            }
        }
        __syncwarp();

#pragma unroll
        for (int ks = 0; ks < 8; ks++) {
            int r = wq * 16 + (lane >> 2);
            int c = ks * 8 + (lane & 3);
            unsigned pah[4], pal[4];
            pah[0] = Ph[r * PSTR + c];
            pah[1] = Ph[(r + 8) * PSTR + c];
            pah[2] = Ph[r * PSTR + c + 4];
            pah[3] = Ph[(r + 8) * PSTR + c + 4];
            pal[0] = Pl[r * PSTR + c];
            pal[1] = Pl[(r + 8) * PSTR + c];
            pal[2] = Pl[r * PSTR + c + 4];
            pal[3] = Pl[(r + 8) * PSTR + c + 4];
#pragma unroll
            for (int nt = 0; nt < 8; nt++) {
                int k = ks * 8 + (lane & 3);
                int n = nt * 8 + (lane >> 2);
                unsigned vbh[2], vbl[2];
                vbh[0] = Vh[k * VSTR + n];
                vbh[1] = Vh[(k + 4) * VSTR + n];
                vbl[0] = Vl[k * VSTR + n];
                vbl[1] = Vl[(k + 4) * VSTR + n];
                mma_tf32(out[nt], pah, vbh);
                mma_tf32(out[nt], pah, vbl);
                mma_tf32(out[nt], pal, vbh);
            }
        }
        __syncwarp();
    }

    if (j_start > 0) {
        float mn0 = fmaxf(m0, 0.f), mn1 = fmaxf(m1, 0.f);
        float esc0 = __expf(m0 - mn0), esc1 = __expf(m1 - mn1);
        float e0 = __expf(0.f - mn0), e1 = __expf(0.f - mn1);
        sum0 = sum0 * esc0 + 4.f * e0;
        sum1 = sum1 * esc1 + 4.f * e1;
#pragma unroll
        for (int nt = 0; nt < 8; nt++) {
            int col = nt * 8 + 2 * (lane & 3);
            out[nt][0] = out[nt][0] * esc0 + e0 * Vg4[col];
            out[nt][1] = out[nt][1] * esc0 + e0 * Vg4[col + 1];
            out[nt][2] = out[nt][2] * esc1 + e1 * Vg4[col];
            out[nt][3] = out[nt][3] * esc1 + e1 * Vg4[col + 1];
        }
    }

    float inv0 = 1.f / sum0, inv1 = 1.f / sum1;
    const int r0 = i0 + wq * 16 + (lane >> 2);
#pragma unroll
    for (int nt = 0; nt < 8; nt++) {
        int cb = h * HDIM + nt * 8 + 2 * (lane & 3);
        *(float2*)(g_O + (size_t)r0 * DMODEL + cb) =
            make_float2(out[nt][0] * inv0, out[nt][1] * inv0);
        *(float2*)(g_O + (size_t)(r0 + 8) * DMODEL + cb) =
            make_float2(out[nt][2] * inv1, out[nt][3] * inv1);
    }
}

// ---------------------------------------------------------------------------
// Global attention (KG/VG, 4 columns) — adds into g_O. Warp per (i, h).
// ---------------------------------------------------------------------------
__global__ __launch_bounds__(128) void global_attn_kernel()
{
    int warp = (blockIdx.x * blockDim.x + threadIdx.x) >> 5;
    int lane = threadIdx.x & 31;
    int h = warp & (NHEADS - 1);
    int i = warp >> 4;
    if (i >= S_LEN) return;

    const float scale = 0.125f;
    const float* Q  = g_P;
    const float* KG = g_P + (size_t)3 * ACT_ELEMS;
    const float* VG = g_P + (size_t)4 * ACT_ELEMS;

    const float* qp = Q + (size_t)i * DMODEL + h * HDIM;
    float q0 = qp[lane], q1 = qp[lane + 32];

    float sg[NGLOB];
    float mg = -3.4e38f;
#pragma unroll
    for (int t = 0; t < NGLOB; t++) {
        const float* kp = KG + (size_t)t * DMODEL + h * HDIM;
        float p = q0 * kp[lane] + q1 * kp[lane + 32];
#pragma unroll
        for (int o = 16; o > 0; o >>= 1) p += __shfl_xor_sync(0xffffffff, p, o);
        sg[t] = p * scale;
        mg = fmaxf(mg, sg[t]);
    }
    float den = 0.f, gsum0 = 0.f, gsum1 = 0.f;
#pragma unroll
    for (int t = 0; t < NGLOB; t++) {
        float e = __expf(sg[t] - mg);
        const float* vp = VG + (size_t)t * DMODEL + h * HDIM;
        den += e;
        gsum0 += e * vp[lane];
        gsum1 += e * vp[lane + 32];
    }
    float ginv = 1.f / den;

    float* op = g_O + (size_t)i * DMODEL + h * HDIM;
    op[lane]      += gsum0 * ginv;
    op[lane + 32] += gsum1 * ginv;
}

// ---------------------------------------------------------------------------
// launch
// ---------------------------------------------------------------------------
extern "C" void kernel_launch(void* const* d_in, const int* in_sizes, int n_in,
                              void* d_out, int out_size)
{
    const float* x     = (const float*)d_in[0];
    const float* cos_t = (const float*)d_in[1];
    const float* sin_t = (const float*)d_in[2];
    const int*   pos   = (const int*)d_in[3];
    const float* W[6];
    W[0] = (const float*)d_in[4];    // Wqs
    W[1] = (const float*)d_in[5];    // Wks
    W[2] = (const float*)d_in[6];    // Wvs
    W[3] = (const float*)d_in[8];    // Wkg  (d_in[7]=Wqg unused)
    W[4] = (const float*)d_in[9];    // Wvg
    W[5] = (const float*)d_in[10];   // Wo
    float* out = (float*)d_out;

    static int attrs_set = 0;
    int attn_smem = ATT_SMEM_WORDS * 4;
    if (!attrs_set) {
        cudaFuncSetAttribute(attn_kernel,
                             cudaFuncAttributeMaxDynamicSharedMemorySize, attn_smem);
        cudaFuncSetAttribute(proj_kernel,
                             cudaFuncAttributeMaxDynamicSharedMemorySize, GEMM_SMEM_BYTES);
        cudaFuncSetAttribute(out_gemm_kernel,
                             cudaFuncAttributeMaxDynamicSharedMemorySize, GEMM_SMEM_BYTES);
        attrs_set = 1;
    }

    unsigned* Sh;
    unsigned* Sl;
    cudaGetSymbolAddress((void**)&Sh, g_Sh);
    cudaGetSymbolAddress((void**)&Sl, g_Sl);

    // split x and the 6 weights into tf32 hi/lo
    split_kernel<<<(ACT_ELEMS / 4 + 255) / 256, 256>>>(x, Sh, Sl, ACT_ELEMS / 4);
    for (int z = 0; z < 6; z++)
        split_kernel<<<(W_ELEMS / 4 + 255) / 256, 256>>>(
            W[z], Sh + ACT_ELEMS + (size_t)z * W_ELEMS,
                  Sl + ACT_ELEMS + (size_t)z * W_ELEMS, W_ELEMS / 4);

    dim3 gp(DMODEL / 128, S_LEN / 128, 5);
    proj_kernel<<<gp, 256, GEMM_SMEM_BYTES>>>();

    dim3 gr((S_LEN * NHEADS * 32) / 256, 2);
    rope_kernel<<<gr, 256>>>(cos_t, sin_t, pos);

    dim3 ga(NHEADS, S_LEN / 64);
    attn_kernel<<<ga, 128, attn_smem>>>();

    global_attn_kernel<<<(S_LEN * NHEADS) / 4, 128>>>();

    // split attention output for the final GEMM (reuses activation slot)
    float* gO;
    cudaGetSymbolAddress((void**)&gO, g_O);
    split_kernel<<<(ACT_ELEMS / 4 + 255) / 256, 256>>>(gO, Sh, Sl, ACT_ELEMS / 4);

    dim3 go(DMODEL / 128, S_LEN / 128);
    out_gemm_kernel<<<go, 256, GEMM_SMEM_BYTES>>>(out);
}